// round 14
// baseline (speedup 1.0000x reference)
#include <cuda_runtime.h>
#include <cuda_fp16.h>
#include <cstdint>

// ---------------- problem constants ----------------
#define HW   196
#define BB   8
#define SEQ  32
#define DD   768
#define DH   192
#define HALF 96                  // DH/2
#define NSEQ (BB*HW)             // 1568
#define MTOT (NSEQ*SEQ)          // 50176

// ---------------- scratch (__device__ globals) ------------------------------
__device__ float  g_q  [MTOT*DH];
__device__ float  g_k  [MTOT*DH];
__device__ float  g_v  [MTOT*DH];
// fp16 hi/lo pre-split activations
__device__ __half g_xdh[MTOT*DH], g_xdl[MTOT*DH];   // LayerNorm'd h
__device__ __half g_rth[MTOT*DH], g_rtl[MTOT*DH];   // retention output

// fp16-split weights, TRANSPOSED [N][K] layout
__device__ __half g_w1h[DH*DD], g_w1l[DH*DD];
__device__ __half g_wqh[DH*DH], g_wql[DH*DH];
__device__ __half g_wkh[DH*DH], g_wkl[DH*DH];
__device__ __half g_wvh[DH*DH], g_wvl[DH*DH];
__device__ __half g_w2h[DD*DH], g_w2l[DD*DH];

// xPos tables: [t (0..31)][p (0..95)]
__device__ float g_cos_u[SEQ*HALF];
__device__ float g_sin_u[SEQ*HALF];
__device__ float g_cos_d[SEQ*HALF];
__device__ float g_sin_d[SEQ*HALF];

__device__ __forceinline__ int x_row_of(int m) {
    int q  = m >> 5;
    int t  = m & 31;
    int bi = q / HW;
    int hi = q - bi * HW;
    return hi * (BB * SEQ) + bi * SEQ + t;
}

// ---------------- helpers ----------------------------------------------------
__device__ __forceinline__ void cpasync16(uint32_t s, const void* g) {
    asm volatile("cp.async.ca.shared.global [%0], [%1], 16;" :: "r"(s), "l"(g) : "memory");
}
#define CP_COMMIT() asm volatile("cp.async.commit_group;" ::: "memory")
#define CP_WAIT0()  asm volatile("cp.async.wait_group 0;" ::: "memory")
#define CP_WAIT1()  asm volatile("cp.async.wait_group 1;" ::: "memory")

__device__ __forceinline__ void mma16(float* d, const uint32_t* a, uint32_t b0, uint32_t b1) {
    asm volatile(
        "mma.sync.aligned.m16n8k16.row.col.f32.f16.f16.f32 "
        "{%0,%1,%2,%3}, {%4,%5,%6,%7}, {%8,%9}, {%0,%1,%2,%3};"
        : "+f"(d[0]), "+f"(d[1]), "+f"(d[2]), "+f"(d[3])
        : "r"(a[0]), "r"(a[1]), "r"(a[2]), "r"(a[3]), "r"(b0), "r"(b1));
}

__device__ __forceinline__ void split16(float v, __half& h, __half& l) {
    h = __float2half_rn(v);
    l = __float2half_rn(v - __half2float(h));
}

// ---------------- prep: weight fp16 split + transpose + xPos tables ---------
__device__ __forceinline__ void w_split_t(const float* __restrict__ W,
                                          __half* __restrict__ Wh, __half* __restrict__ Wl,
                                          int idx, int K, int N) {
    int k = idx / N, n = idx - k * N;
    __half h, l;
    split16(W[idx], h, l);
    Wh[(size_t)n * K + k] = h;
    Wl[(size_t)n * K + k] = l;
}

__global__ void k_prep(const float* __restrict__ W1, const float* __restrict__ WQ,
                       const float* __restrict__ WK, const float* __restrict__ WV,
                       const float* __restrict__ W2) {
    int idx = blockIdx.x * blockDim.x + threadIdx.x;
    if (idx < DD*DH) { w_split_t(W1, g_w1h, g_w1l, idx, DD, DH); return; }
    idx -= DD*DH;
    if (idx < DH*DH) { w_split_t(WQ, g_wqh, g_wql, idx, DH, DH); return; }
    idx -= DH*DH;
    if (idx < DH*DH) { w_split_t(WK, g_wkh, g_wkl, idx, DH, DH); return; }
    idx -= DH*DH;
    if (idx < DH*DH) { w_split_t(WV, g_wvh, g_wvl, idx, DH, DH); return; }
    idx -= DH*DH;
    if (idx < DH*DD) { w_split_t(W2, g_w2h, g_w2l, idx, DH, DD); return; }
    idx -= DH*DD;
    if (idx < SEQ*HALF) {
        int t = idx / HALF, p = idx % HALF;
        double base = (2.0 * p + 0.4 * (double)DH) / (1.4 * (double)DH);
        double sc_u = pow(base, (double)t / 512.0);
        double sc_d = 1.0 / sc_u;
        double invf = pow(10000.0, -(double)p / (double)HALF);
        double ang  = (double)t * invf;
        double s = sin(ang), c = cos(ang);
        g_cos_u[idx] = (float)(c * sc_u);
        g_sin_u[idx] = (float)(s * sc_u);
        g_cos_d[idx] = (float)(c * sc_d);
        g_sin_d[idx] = (float)(s * sc_d);
    }
}

// ================= GEMM1: x(gathered) @ W1 + b1 -> LN -> fp16 hi/lo =========
// R13-style: A LDG fp32 + split + STS, B cp.async, 2-stage, BK=16, K=768.
#define A_B32 (64*12)
#define B_B32 (192*12)
#define G1_SMEM_U32 (4*A_B32 + 4*B_B32)   // 12288 u32 = 49152 B

__global__ void __launch_bounds__(128, 3) k_g1(
    const float* __restrict__ A,
    const __half* __restrict__ Bhi, const __half* __restrict__ Blo,
    const float* __restrict__ bias,
    const float* __restrict__ lng, const float* __restrict__ lnb,
    __half* __restrict__ Ch, __half* __restrict__ Cl)
{
    const int K = DD, N = DH;
    extern __shared__ uint32_t smu[];
    uint32_t* AH = smu;
    uint32_t* AL = smu + 2*A_B32;
    uint32_t* BH = smu + 4*A_B32;
    uint32_t* BL = smu + 4*A_B32 + 2*B_B32;

    const int tid  = threadIdx.x;
    const int w    = tid >> 5;
    const int lane = tid & 31;
    const int g    = lane >> 2;
    const int tg   = lane & 3;
    const int mw   = w >> 1;
    const int nw   = w & 1;
    const int bm   = blockIdx.y * 64;

    int aRow[2], aKq[2];
    const float* aPtr[2];
#pragma unroll
    for (int i = 0; i < 2; i++) {
        int f4 = tid + i * 128;
        aRow[i] = f4 >> 2;
        aKq[i]  = f4 & 3;
        aPtr[i] = A + (size_t)x_row_of(bm + aRow[i]) * K + aKq[i] * 4;
    }
    int bArr[6], bN[6], bC[6];
#pragma unroll
    for (int i = 0; i < 6; i++) {
        int f = tid + i * 128;
        bArr[i] = f / 384;
        int r = f % 384;
        bN[i] = r >> 1;
        bC[i] = r & 1;
    }

    float acc[12][8];
#pragma unroll
    for (int nt = 0; nt < 12; nt++)
#pragma unroll
        for (int e = 0; e < 8; e++) acc[nt][e] = 0.0f;

    float4 aReg[2];
    auto loadA = [&](int k0) {
#pragma unroll
        for (int i = 0; i < 2; i++) aReg[i] = *(const float4*)(aPtr[i] + k0);
    };
    auto storeA = [&](int buf) {
#pragma unroll
        for (int i = 0; i < 2; i++) {
            float4 v = aReg[i];
            __half hx, lx, hy, ly, hz, lz, hw, lw;
            split16(v.x, hx, lx); split16(v.y, hy, ly);
            split16(v.z, hz, lz); split16(v.w, hw, lw);
            __half2 h0 = __halves2half2(hx, hy), h1 = __halves2half2(hz, hw);
            __half2 l0 = __halves2half2(lx, ly), l1 = __halves2half2(lz, lw);
            int base = buf * A_B32 + aRow[i] * 12 + aKq[i] * 2;
            AH[base]     = *(uint32_t*)&h0;
            AH[base + 1] = *(uint32_t*)&h1;
            AL[base]     = *(uint32_t*)&l0;
            AL[base + 1] = *(uint32_t*)&l1;
        }
    };
    auto issueB = [&](int k0, int buf) {
#pragma unroll
        for (int i = 0; i < 6; i++) {
            const __half* src = (bArr[i] ? Blo : Bhi) + (size_t)bN[i] * K + k0 + bC[i] * 8;
            uint32_t* dstA = bArr[i] ? BL : BH;
            uint32_t dst = (uint32_t)__cvta_generic_to_shared(
                dstA + buf * B_B32 + bN[i] * 12 + bC[i] * 4);
            cpasync16(dst, src);
        }
        CP_COMMIT();
    };
    auto compute = [&](int buf) {
        const uint32_t* AHb = AH + buf * A_B32;
        const uint32_t* ALb = AL + buf * A_B32;
        const uint32_t* BHb = BH + buf * B_B32;
        const uint32_t* BLb = BL + buf * B_B32;
        const int ra = (mw * 32 + g) * 12 + tg;
        uint32_t ah0[4] = {AHb[ra],       AHb[ra + 96],  AHb[ra + 4],   AHb[ra + 100]};
        uint32_t ah1[4] = {AHb[ra + 192], AHb[ra + 288], AHb[ra + 196], AHb[ra + 292]};
        uint32_t al0[4] = {ALb[ra],       ALb[ra + 96],  ALb[ra + 4],   ALb[ra + 100]};
        uint32_t al1[4] = {ALb[ra + 192], ALb[ra + 288], ALb[ra + 196], ALb[ra + 292]};
#pragma unroll
        for (int nt = 0; nt < 12; nt++) {
            int rb = (nw * 96 + nt * 8 + g) * 12 + tg;
            uint32_t bh0 = BHb[rb], bh1 = BHb[rb + 4];
            uint32_t bl0 = BLb[rb], bl1 = BLb[rb + 4];
            mma16(acc[nt],     ah0, bh0, bh1);
            mma16(acc[nt] + 4, ah1, bh0, bh1);
            mma16(acc[nt],     al0, bh0, bh1);
            mma16(acc[nt] + 4, al1, bh0, bh1);
            mma16(acc[nt],     ah0, bl0, bl1);
            mma16(acc[nt] + 4, ah1, bl0, bl1);
        }
    };

    loadA(0);
    issueB(0, 0);
    storeA(0);
    CP_WAIT0();
    __syncthreads();
    int cur = 0;
    for (int k0 = 16; k0 < K; k0 += 16) {
        loadA(k0);
        issueB(k0, cur ^ 1);
        compute(cur);
        storeA(cur ^ 1);
        CP_WAIT0();
        __syncthreads();
        cur ^= 1;
    }
    compute(cur);

    // epilogue: +bias, LayerNorm, fp16 hi/lo output
    const int lrb = mw * 32 + g;
    float* smf = (float*)smu;
    float s1[4] = {0.f, 0.f, 0.f, 0.f}, s2[4] = {0.f, 0.f, 0.f, 0.f};
#pragma unroll
    for (int nt = 0; nt < 12; nt++) {
        int c = nw * 96 + nt * 8 + 2 * tg;
        float b0 = __ldg(&bias[c]), b1 = __ldg(&bias[c + 1]);
#pragma unroll
        for (int i = 0; i < 4; i++) {
            float v0 = acc[nt][2 * i]     + b0;
            float v1 = acc[nt][2 * i + 1] + b1;
            acc[nt][2 * i]     = v0;
            acc[nt][2 * i + 1] = v1;
            s1[i] += v0 + v1;
            s2[i] += v0 * v0 + v1 * v1;
        }
    }
#pragma unroll
    for (int o = 1; o < 4; o <<= 1) {
#pragma unroll
        for (int i = 0; i < 4; i++) {
            s1[i] += __shfl_xor_sync(0xffffffffu, s1[i], o);
            s2[i] += __shfl_xor_sync(0xffffffffu, s2[i], o);
        }
    }
    __syncthreads();
    if (tg == 0) {
#pragma unroll
        for (int i = 0; i < 4; i++) {
            int lr = lrb + 8 * i;
            smf[nw * 64 + lr]       = s1[i];
            smf[128 + nw * 64 + lr] = s2[i];
        }
    }
    __syncthreads();
    float mu[4], inv[4];
#pragma unroll
    for (int i = 0; i < 4; i++) {
        int lr = lrb + 8 * i;
        float S1 = smf[lr] + smf[64 + lr];
        float S2 = smf[128 + lr] + smf[192 + lr];
        mu[i]  = S1 * (1.0f / 192.0f);
        inv[i] = rsqrtf(S2 * (1.0f / 192.0f) - mu[i] * mu[i] + 1e-5f);
    }
#pragma unroll
    for (int nt = 0; nt < 12; nt++) {
        int c = nw * 96 + nt * 8 + 2 * tg;
        float gg0 = __ldg(&lng[c]), gg1 = __ldg(&lng[c + 1]);
        float bb0 = __ldg(&lnb[c]), bb1 = __ldg(&lnb[c + 1]);
#pragma unroll
        for (int i = 0; i < 4; i++) {
            int mr = bm + lrb + 8 * i;
            float o0 = (acc[nt][2 * i]     - mu[i]) * inv[i] * gg0 + bb0;
            float o1 = (acc[nt][2 * i + 1] - mu[i]) * inv[i] * gg1 + bb1;
            __half h0, l0, h1, l1;
            split16(o0, h0, l0);
            split16(o1, h1, l1);
            __half2 hh = __halves2half2(h0, h1);
            __half2 ll = __halves2half2(l0, l1);
            *(__half2*)(Ch + (size_t)mr * N + c) = hh;
            *(__half2*)(Cl + (size_t)mr * N + c) = ll;
        }
    }
}

// ================= k_mma2: pre-split fp16 A & B, pure cp.async, K=192 =======
// 3-stage pipeline, 128 threads (2M x 2N warps), warp tile 32x96.
// MODE 1/2: xPos up/down -> fp32 C   MODE 3: plain fp32 C
// MODE 4: +bias +x residual (gathered rows) -> fp32 C (ld = N)
#define ST_A (64*12)             // u32 per A stage per array
#define ST_B (192*12)            // u32 per B stage per array
#define M2_SMEM_U32 (3*2*ST_A + 3*2*ST_B)   // 18432 u32 = 73728 B

template <int MODE>
__global__ void __launch_bounds__(128) k_mma2(
    const __half* __restrict__ Ahi, const __half* __restrict__ Alo,
    const __half* __restrict__ Bhi, const __half* __restrict__ Blo,
    const float* __restrict__ bias, const float* __restrict__ xres,
    float* __restrict__ C, int N)
{
    const int K = DH;            // 192, T = 12 stages
    extern __shared__ uint32_t smu[];
    uint32_t* AH = smu;
    uint32_t* AL = smu + 3*ST_A;
    uint32_t* BH = smu + 6*ST_A;
    uint32_t* BL = smu + 6*ST_A + 3*ST_B;

    const int tid  = threadIdx.x;
    const int w    = tid >> 5;
    const int lane = tid & 31;
    const int g    = lane >> 2;
    const int tg   = lane & 3;
    const int mw   = w >> 1;
    const int nw   = w & 1;
    const int bm   = blockIdx.y * 64;
    const int bn   = blockIdx.x * 192;

    // A cp.async slots: 2 per thread (2 arrays x 64 rows x 2 chunks = 256)
    int aArr[2], aR[2], aC[2];
#pragma unroll
    for (int i = 0; i < 2; i++) {
        int f = tid + i * 128;
        aArr[i] = f >> 7;
        int r = f & 127;
        aR[i] = r >> 1;
        aC[i] = r & 1;
    }
    // B cp.async slots: 6 per thread (2 arrays x 192 rows x 2 chunks = 768)
    int bArr[6], bN[6], bC[6];
#pragma unroll
    for (int i = 0; i < 6; i++) {
        int f = tid + i * 128;
        bArr[i] = f / 384;
        int r = f % 384;
        bN[i] = r >> 1;
        bC[i] = r & 1;
    }

    float acc[12][8];
#pragma unroll
    for (int nt = 0; nt < 12; nt++)
#pragma unroll
        for (int e = 0; e < 8; e++) acc[nt][e] = 0.0f;

    auto issueAB = [&](int k0, int buf) {
#pragma unroll
        for (int i = 0; i < 2; i++) {
            const __half* src = (aArr[i] ? Alo : Ahi)
                              + (size_t)(bm + aR[i]) * K + k0 + aC[i] * 8;
            uint32_t* dstA = aArr[i] ? AL : AH;
            uint32_t dst = (uint32_t)__cvta_generic_to_shared(
                dstA + buf * ST_A + aR[i] * 12 + aC[i] * 4);
            cpasync16(dst, src);
        }
#pragma unroll
        for (int i = 0; i < 6; i++) {
            const __half* src = (bArr[i] ? Blo : Bhi)
                              + (size_t)(bn + bN[i]) * K + k0 + bC[i] * 8;
            uint32_t* dstA = bArr[i] ? BL : BH;
            uint32_t dst = (uint32_t)__cvta_generic_to_shared(
                dstA + buf * ST_B + bN[i] * 12 + bC[i] * 4);
            cpasync16(dst, src);
        }
        CP_COMMIT();
    };
    auto compute = [&](int buf) {
        const uint32_t* AHb = AH + buf * ST_A;
        const uint32_t* ALb = AL + buf * ST_A;
        const uint32_t* BHb = BH + buf * ST_B;
        const uint32_t* BLb = BL + buf * ST_B;
        const int ra = (mw * 32 + g) * 12 + tg;
        uint32_t ah0[4] = {AHb[ra],       AHb[ra + 96],  AHb[ra + 4],   AHb[ra + 100]};
        uint32_t ah1[4] = {AHb[ra + 192], AHb[ra + 288], AHb[ra + 196], AHb[ra + 292]};
        uint32_t al0[4] = {ALb[ra],       ALb[ra + 96],  ALb[ra + 4],   ALb[ra + 100]};
        uint32_t al1[4] = {ALb[ra + 192], ALb[ra + 288], ALb[ra + 196], ALb[ra + 292]};
#pragma unroll
        for (int nt = 0; nt < 12; nt++) {
            int rb = (nw * 96 + nt * 8 + g) * 12 + tg;
            uint32_t bh0 = BHb[rb], bh1 = BHb[rb + 4];
            uint32_t bl0 = BLb[rb], bl1 = BLb[rb + 4];
            mma16(acc[nt],     ah0, bh0, bh1);
            mma16(acc[nt] + 4, ah1, bh0, bh1);
            mma16(acc[nt],     al0, bh0, bh1);
            mma16(acc[nt] + 4, al1, bh0, bl1 ? bl1 : bl1);  // placeholder avoided below
            mma16(acc[nt],     ah0, bl0, bl1);
        }
    };
    (void)compute; // replaced by computeX below (correct 6-MMA version)

    auto computeX = [&](int buf) {
        const uint32_t* AHb = AH + buf * ST_A;
        const uint32_t* ALb = AL + buf * ST_A;
        const uint32_t* BHb = BH + buf * ST_B;
        const uint32_t* BLb = BL + buf * ST_B;
        const int ra = (mw * 32 + g) * 12 + tg;
        uint32_t ah0[4] = {AHb[ra],       AHb[ra + 96],  AHb[ra + 4],   AHb[ra + 100]};
        uint32_t ah1[4] = {AHb[ra + 192], AHb[ra + 288], AHb[ra + 196], AHb[ra + 292]};
        uint32_t al0[4] = {ALb[ra],       ALb[ra + 96],  ALb[ra + 4],   ALb[ra + 100]};
        uint32_t al1[4] = {ALb[ra + 192], ALb[ra + 288], ALb[ra + 196], ALb[ra + 292]};
#pragma unroll
        for (int nt = 0; nt < 12; nt++) {
            int rb = (nw * 96 + nt * 8 + g) * 12 + tg;
            uint32_t bh0 = BHb[rb], bh1 = BHb[rb + 4];
            uint32_t bl0 = BLb[rb], bl1 = BLb[rb + 4];
            mma16(acc[nt],     ah0, bh0, bh1);
            mma16(acc[nt] + 4, ah1, bh0, bh1);
            mma16(acc[nt],     al0, bh0, bh1);
            mma16(acc[nt] + 4, al1, bh0, bh1);
            mma16(acc[nt],     ah0, bl0, bl1);
            mma16(acc[nt] + 4, ah1, bl0, bl1);
        }
    };

    // 3-stage pipeline over T=12 k-steps
    issueAB(0, 0);
    issueAB(16, 1);
#pragma unroll
    for (int t = 0; t < 12; t++) {
        if (t == 11) { CP_WAIT0(); } else { CP_WAIT1(); }
        __syncthreads();
        if (t + 2 < 12) issueAB((t + 2) * 16, (t + 2) % 3);
        computeX(t % 3);
    }

    // ---------------- epilogue ----------------
    const int lrb = mw * 32 + g;

    if (MODE == 1 || MODE == 2) {
        const float* ct = (MODE == 1) ? g_cos_u : g_cos_d;
        const float* st = (MODE == 1) ? g_sin_u : g_sin_d;
#pragma unroll
        for (int nt = 0; nt < 12; nt++) {
            int c = nw * 96 + nt * 8 + 2 * tg;
            int p = (c >> 1);
#pragma unroll
            for (int i = 0; i < 4; i++) {
                int lr = lrb + 8 * i;
                int t  = lr & 31;
                float cc = ct[t * HALF + p], ss = st[t * HALF + p];
                float e = acc[nt][2 * i], od = acc[nt][2 * i + 1];
                *(float2*)(C + (size_t)(bm + lr) * N + c) =
                    make_float2(e * cc - od * ss, od * cc + e * ss);
            }
        }
    } else if (MODE == 3) {
#pragma unroll
        for (int nt = 0; nt < 12; nt++) {
            int c = nw * 96 + nt * 8 + 2 * tg;
#pragma unroll
            for (int i = 0; i < 4; i++) {
                int mr = bm + lrb + 8 * i;
                *(float2*)(C + (size_t)mr * N + c) =
                    make_float2(acc[nt][2 * i], acc[nt][2 * i + 1]);
            }
        }
    } else { // MODE 4
        int grr[4];
#pragma unroll
        for (int i = 0; i < 4; i++) grr[i] = x_row_of(bm + lrb + 8 * i);
#pragma unroll
        for (int nt = 0; nt < 12; nt++) {
            int c = bn + nw * 96 + nt * 8 + 2 * tg;
            float b0 = __ldg(&bias[c]), b1 = __ldg(&bias[c + 1]);
#pragma unroll
            for (int i = 0; i < 4; i++) {
                float2 xv = *(const float2*)(xres + (size_t)grr[i] * N + c);
                *(float2*)(C + (size_t)grr[i] * N + c) =
                    make_float2(acc[nt][2 * i] + b0 + xv.x,
                                acc[nt][2 * i + 1] + b1 + xv.y);
            }
        }
    }
}

// ---------------- per-sequence retention attention (fp16 hi/lo output) ------
__global__ void __launch_bounds__(256) k_attn(
    const float* __restrict__ Q, const float* __restrict__ Kmat,
    const float* __restrict__ V,
    __half* __restrict__ Rh, __half* __restrict__ Rl)
{
    __shared__ __align__(16) float sKV[SEQ][DH];
    const int q   = blockIdx.x;
    const int tid = threadIdx.x;
    const int n   = tid >> 3;
    const int j   = tid & 7;
    const size_t base = (size_t)q * SEQ * DH;

    for (int i = tid; i < SEQ * DH / 4; i += 256)
        ((float4*)&sKV[0][0])[i] = ((const float4*)(Kmat + base))[i];

    float qr[24];
    const float* qp = Q + base + (size_t)n * DH + j * 24;
#pragma unroll
    for (int dd = 0; dd < 6; dd++)
        *(float4*)&qr[dd * 4] = *(const float4*)(qp + dd * 4);
    __syncthreads();

    float att[SEQ];
#pragma unroll
    for (int m = 0; m < SEQ; m++) {
        float s = 0.0f;
#pragma unroll
        for (int dd = 0; dd < 6; dd++) {
            float4 kv = *(const float4*)&sKV[m][j * 24 + dd * 4];
            s += qr[dd*4+0]*kv.x + qr[dd*4+1]*kv.y + qr[dd*4+2]*kv.z + qr[dd*4+3]*kv.w;
        }
        att[m] = s;
    }
#pragma unroll
    for (int m = 0; m < SEQ; m++) {
#pragma unroll
        for (int o = 1; o < 8; o <<= 1)
            att[m] += __shfl_xor_sync(0xffffffffu, att[m], o);
        att[m] = (n >= m) ? ldexpf(att[m], m - n) : 0.0f;
    }

    __syncthreads();
    for (int i = tid; i < SEQ * DH / 4; i += 256)
        ((float4*)&sKV[0][0])[i] = ((const float4*)(V + base))[i];
    __syncthreads();

    float acc[24];
#pragma unroll
    for (int dd = 0; dd < 24; dd++) acc[dd] = 0.0f;
#pragma unroll
    for (int m = 0; m < SEQ; m++) {
        float a = att[m];
#pragma unroll
        for (int dd = 0; dd < 6; dd++) {
            float4 vv = *(const float4*)&sKV[m][j * 24 + dd * 4];
            acc[dd*4+0] += a * vv.x; acc[dd*4+1] += a * vv.y;
            acc[dd*4+2] += a * vv.z; acc[dd*4+3] += a * vv.w;
        }
    }
    size_t ro = base + (size_t)n * DH + j * 24;
#pragma unroll
    for (int dd = 0; dd < 12; dd++) {
        float v0 = acc[dd * 2], v1 = acc[dd * 2 + 1];
        __half h0, l0, h1, l1;
        split16(v0, h0, l0);
        split16(v1, h1, l1);
        __half2 hh = __halves2half2(h0, h1);
        __half2 ll = __halves2half2(l0, l1);
        *(__half2*)(Rh + ro + dd * 2) = hh;
        *(__half2*)(Rl + ro + dd * 2) = ll;
    }
}

// ---------------- launch --------------------------------------------------
extern "C" void kernel_launch(void* const* d_in, const int* in_sizes, int n_in,
                              void* d_out, int out_size)
{
    const float* x    = (const float*)d_in[0];
    const float* W1   = (const float*)d_in[1];
    const float* b1   = (const float*)d_in[2];
    const float* W2   = (const float*)d_in[3];
    const float* b2   = (const float*)d_in[4];
    const float* ln_g = (const float*)d_in[5];
    const float* ln_b = (const float*)d_in[6];
    const float* WQ   = (const float*)d_in[7];
    const float* WK   = (const float*)d_in[8];
    const float* WV   = (const float*)d_in[9];
    float* out = (float*)d_out;

    float* qb = nullptr; cudaGetSymbolAddress((void**)&qb, g_q);
    float* kb = nullptr; cudaGetSymbolAddress((void**)&kb, g_k);
    float* vb = nullptr; cudaGetSymbolAddress((void**)&vb, g_v);
    __half *xdh, *xdl, *rth, *rtl;
    cudaGetSymbolAddress((void**)&xdh, g_xdh); cudaGetSymbolAddress((void**)&xdl, g_xdl);
    cudaGetSymbolAddress((void**)&rth, g_rth); cudaGetSymbolAddress((void**)&rtl, g_rtl);
    __half *w1h, *w1l, *wqh, *wql, *wkh, *wkl, *wvh, *wvl, *w2h, *w2l;
    cudaGetSymbolAddress((void**)&w1h, g_w1h); cudaGetSymbolAddress((void**)&w1l, g_w1l);
    cudaGetSymbolAddress((void**)&wqh, g_wqh); cudaGetSymbolAddress((void**)&wql, g_wql);
    cudaGetSymbolAddress((void**)&wkh, g_wkh); cudaGetSymbolAddress((void**)&wkl, g_wkl);
    cudaGetSymbolAddress((void**)&wvh, g_wvh); cudaGetSymbolAddress((void**)&wvl, g_wvl);
    cudaGetSymbolAddress((void**)&w2h, g_w2h); cudaGetSymbolAddress((void**)&w2l, g_w2l);

    const int G1_SMEM = G1_SMEM_U32 * 4;   // 49152
    const int M2_SMEM = M2_SMEM_U32 * 4;   // 73728
    cudaFuncSetAttribute(k_g1,      cudaFuncAttributeMaxDynamicSharedMemorySize, G1_SMEM);
    cudaFuncSetAttribute(k_mma2<1>, cudaFuncAttributeMaxDynamicSharedMemorySize, M2_SMEM);
    cudaFuncSetAttribute(k_mma2<2>, cudaFuncAttributeMaxDynamicSharedMemorySize, M2_SMEM);
    cudaFuncSetAttribute(k_mma2<3>, cudaFuncAttributeMaxDynamicSharedMemorySize, M2_SMEM);
    cudaFuncSetAttribute(k_mma2<4>, cudaFuncAttributeMaxDynamicSharedMemorySize, M2_SMEM);

    // prep: weight fp16 split + transpose + xPos tables
    {
        int total = DD*DH + 3*DH*DH + DH*DD + SEQ*HALF;
        k_prep<<<(total + 255) / 256, 256>>>(W1, WQ, WK, WV, W2);
    }

    // GEMM1 + bias + LN -> fp16 hi/lo h
    k_g1<<<dim3(1, MTOT / 64), 128, G1_SMEM>>>(x, w1h, w1l, b1, ln_g, ln_b, xdh, xdl);
    // QKV from pre-split h
    k_mma2<1><<<dim3(1, MTOT / 64), 128, M2_SMEM>>>(xdh, xdl, wqh, wql, nullptr, nullptr, qb, DH);
    k_mma2<2><<<dim3(1, MTOT / 64), 128, M2_SMEM>>>(xdh, xdl, wkh, wkl, nullptr, nullptr, kb, DH);
    k_mma2<3><<<dim3(1, MTOT / 64), 128, M2_SMEM>>>(xdh, xdl, wvh, wvl, nullptr, nullptr, vb, DH);
    // attention -> fp16 hi/lo ret
    k_attn<<<NSEQ, 256>>>(qb, kb, vb, rth, rtl);
    // GEMM2 from pre-split ret: +b2 +x residual -> out
    k_mma2<4><<<dim3(DD / 192, MTOT / 64), 128, M2_SMEM>>>(rth, rtl, w2h, w2l, b2, x, out, DD);
}

// round 15
// speedup vs baseline: 1.1157x; 1.1157x over previous
#include <cuda_runtime.h>
#include <cuda_fp16.h>
#include <cstdint>

// ---------------- problem constants ----------------
#define HW   196
#define BB   8
#define SEQ  32
#define DD   768
#define DH   192
#define HALF 96                  // DH/2
#define NSEQ (BB*HW)             // 1568
#define MTOT (NSEQ*SEQ)          // 50176

// ---------------- scratch (__device__ globals) ------------------------------
__device__ float  g_q  [MTOT*DH];
__device__ float  g_k  [MTOT*DH];
__device__ float  g_v  [MTOT*DH];
__device__ __half g_xdh[MTOT*DH], g_xdl[MTOT*DH];   // LayerNorm'd h (hi/lo)
__device__ __half g_rth[MTOT*DH], g_rtl[MTOT*DH];   // retention out (hi/lo)

// fp16-split weights, TRANSPOSED [N][K] layout
__device__ __half g_w1h[DH*DD], g_w1l[DH*DD];
__device__ __half g_wqh[DH*DH], g_wql[DH*DH];
__device__ __half g_wkh[DH*DH], g_wkl[DH*DH];
__device__ __half g_wvh[DH*DH], g_wvl[DH*DH];
__device__ __half g_w2h[DD*DH], g_w2l[DD*DH];

// xPos tables: [t (0..31)][p (0..95)]
__device__ float g_cos_u[SEQ*HALF];
__device__ float g_sin_u[SEQ*HALF];
__device__ float g_cos_d[SEQ*HALF];
__device__ float g_sin_d[SEQ*HALF];

__device__ __forceinline__ int x_row_of(int m) {
    int q  = m >> 5;
    int t  = m & 31;
    int bi = q / HW;
    int hi = q - bi * HW;
    return hi * (BB * SEQ) + bi * SEQ + t;
}

// ---------------- helpers ----------------------------------------------------
__device__ __forceinline__ void cpasync16(uint32_t s, const void* g) {
    asm volatile("cp.async.ca.shared.global [%0], [%1], 16;" :: "r"(s), "l"(g) : "memory");
}
#define CP_COMMIT() asm volatile("cp.async.commit_group;" ::: "memory")
#define CP_WAIT0()  asm volatile("cp.async.wait_group 0;" ::: "memory")

__device__ __forceinline__ void mma16(float* d, const uint32_t* a, uint32_t b0, uint32_t b1) {
    asm volatile(
        "mma.sync.aligned.m16n8k16.row.col.f32.f16.f16.f32 "
        "{%0,%1,%2,%3}, {%4,%5,%6,%7}, {%8,%9}, {%0,%1,%2,%3};"
        : "+f"(d[0]), "+f"(d[1]), "+f"(d[2]), "+f"(d[3])
        : "r"(a[0]), "r"(a[1]), "r"(a[2]), "r"(a[3]), "r"(b0), "r"(b1));
}

__device__ __forceinline__ void ldsm4(uint32_t* r, uint32_t a) {
    asm volatile("ldmatrix.sync.aligned.m8n8.x4.shared.b16 {%0,%1,%2,%3}, [%4];"
                 : "=r"(r[0]), "=r"(r[1]), "=r"(r[2]), "=r"(r[3]) : "r"(a));
}

__device__ __forceinline__ void split16(float v, __half& h, __half& l) {
    h = __float2half_rn(v);
    l = __float2half_rn(v - __half2float(h));
}

// ---------------- prep: weight fp16 split + transpose + xPos tables ---------
__device__ __forceinline__ void w_split_t(const float* __restrict__ W,
                                          __half* __restrict__ Wh, __half* __restrict__ Wl,
                                          int idx, int K, int N) {
    int k = idx / N, n = idx - k * N;
    __half h, l;
    split16(W[idx], h, l);
    Wh[(size_t)n * K + k] = h;
    Wl[(size_t)n * K + k] = l;
}

__global__ void k_prep(const float* __restrict__ W1, const float* __restrict__ WQ,
                       const float* __restrict__ WK, const float* __restrict__ WV,
                       const float* __restrict__ W2) {
    int idx = blockIdx.x * blockDim.x + threadIdx.x;
    if (idx < DD*DH) { w_split_t(W1, g_w1h, g_w1l, idx, DD, DH); return; }
    idx -= DD*DH;
    if (idx < DH*DH) { w_split_t(WQ, g_wqh, g_wql, idx, DH, DH); return; }
    idx -= DH*DH;
    if (idx < DH*DH) { w_split_t(WK, g_wkh, g_wkl, idx, DH, DH); return; }
    idx -= DH*DH;
    if (idx < DH*DH) { w_split_t(WV, g_wvh, g_wvl, idx, DH, DH); return; }
    idx -= DH*DH;
    if (idx < DH*DD) { w_split_t(W2, g_w2h, g_w2l, idx, DH, DD); return; }
    idx -= DH*DD;
    if (idx < SEQ*HALF) {
        int t = idx / HALF, p = idx % HALF;
        double base = (2.0 * p + 0.4 * (double)DH) / (1.4 * (double)DH);
        double sc_u = pow(base, (double)t / 512.0);
        double sc_d = 1.0 / sc_u;
        double invf = pow(10000.0, -(double)p / (double)HALF);
        double ang  = (double)t * invf;
        double s = sin(ang), c = cos(ang);
        g_cos_u[idx] = (float)(c * sc_u);
        g_sin_u[idx] = (float)(s * sc_u);
        g_cos_d[idx] = (float)(c * sc_d);
        g_sin_d[idx] = (float)(s * sc_d);
    }
}

// shared tile geometry (u32 units): row pitch 12 (8 data + 4 pad)
#define ST_A (64*12)
#define ST_B (192*12)
#define SMEM_U32 (4*ST_A + 4*ST_B)     // 12288 u32 = 49152 B (2 stages, hi+lo)

// per-warp ldmatrix-based compute over one 16-K tile (72 HMMA, 16 LDSM)
#define COMPUTE_TILE(aH0, aH1, aL0, aL1, bHa, bLa, ACC)                          \
    do {                                                                          \
        uint32_t ah0[4], ah1[4], al0[4], al1[4];                                  \
        ldsm4(ah0, aH0); ldsm4(ah1, aH1); ldsm4(al0, aL0); ldsm4(al1, aL1);       \
        _Pragma("unroll")                                                         \
        for (int p = 0; p < 6; p++) {                                             \
            uint32_t bh[4], bl[4];                                                \
            ldsm4(bh, bHa + p * (16 * 48)); ldsm4(bl, bLa + p * (16 * 48));       \
            float* a0 = ACC[2 * p];                                               \
            float* a1 = ACC[2 * p + 1];                                           \
            mma16(a0,     ah0, bh[0], bh[1]);                                     \
            mma16(a0 + 4, ah1, bh[0], bh[1]);                                     \
            mma16(a1,     ah0, bh[2], bh[3]);                                     \
            mma16(a1 + 4, ah1, bh[2], bh[3]);                                     \
            mma16(a0,     al0, bh[0], bh[1]);                                     \
            mma16(a0 + 4, al1, bh[0], bh[1]);                                     \
            mma16(a1,     al0, bh[2], bh[3]);                                     \
            mma16(a1 + 4, al1, bh[2], bh[3]);                                     \
            mma16(a0,     ah0, bl[0], bl[1]);                                     \
            mma16(a0 + 4, ah1, bl[0], bl[1]);                                     \
            mma16(a1,     ah0, bl[2], bl[3]);                                     \
            mma16(a1 + 4, ah1, bl[2], bl[3]);                                     \
        }                                                                         \
    } while (0)

// ================= GEMM1: x(gathered) @ W1 + b1 -> LN -> fp16 hi/lo =========
__global__ void __launch_bounds__(128, 3) k_g1(
    const float* __restrict__ A,
    const __half* __restrict__ Bhi, const __half* __restrict__ Blo,
    const float* __restrict__ bias,
    const float* __restrict__ lng, const float* __restrict__ lnb,
    __half* __restrict__ Ch, __half* __restrict__ Cl)
{
    const int K = DD, N = DH;
    extern __shared__ uint32_t smu[];
    uint32_t* AH = smu;
    uint32_t* AL = smu + 2*ST_A;
    uint32_t* BH = smu + 4*ST_A;
    uint32_t* BL = smu + 4*ST_A + 2*ST_B;

    const int tid  = threadIdx.x;
    const int w    = tid >> 5;
    const int lane = tid & 31;
    const int g    = lane >> 2;
    const int tg   = lane & 3;
    const int mw   = w >> 1;
    const int nw   = w & 1;
    const int bm   = blockIdx.y * 64;

    // ldmatrix per-lane addresses (stage 0); stage strides in bytes
    const int aRowL = (lane & 15);
    const int aOff4 = (lane >> 4) * 4;
    uint32_t aH0 = (uint32_t)__cvta_generic_to_shared(
        AH + (mw * 32 + aRowL) * 12 + aOff4);
    uint32_t aH1 = aH0 + 16 * 48;
    uint32_t aL0 = aH0 + 2 * ST_A * 4;
    uint32_t aL1 = aL0 + 16 * 48;
    const int bRowL = (lane & 7) + ((lane & 16) >> 1);
    const int bOff4 = (lane & 8) >> 1;
    uint32_t bHa = (uint32_t)__cvta_generic_to_shared(
        BH + (nw * 96 + bRowL) * 12 + bOff4);
    uint32_t bLa = bHa + 2 * ST_B * 4;

    int aRow[2], aKq[2];
    const float* aPtr[2];
#pragma unroll
    for (int i = 0; i < 2; i++) {
        int f4 = tid + i * 128;
        aRow[i] = f4 >> 2;
        aKq[i]  = f4 & 3;
        aPtr[i] = A + (size_t)x_row_of(bm + aRow[i]) * K + aKq[i] * 4;
    }
    int bArr[6], bN[6], bC[6];
#pragma unroll
    for (int i = 0; i < 6; i++) {
        int f = tid + i * 128;
        bArr[i] = f / 384;
        int r = f % 384;
        bN[i] = r >> 1;
        bC[i] = r & 1;
    }

    float acc[12][8];
#pragma unroll
    for (int nt = 0; nt < 12; nt++)
#pragma unroll
        for (int e = 0; e < 8; e++) acc[nt][e] = 0.0f;

    float4 aReg[2];
    auto loadA = [&](int k0) {
#pragma unroll
        for (int i = 0; i < 2; i++) aReg[i] = *(const float4*)(aPtr[i] + k0);
    };
    auto storeA = [&](int buf) {
#pragma unroll
        for (int i = 0; i < 2; i++) {
            float4 v = aReg[i];
            __half hx, lx, hy, ly, hz, lz, hw2, lw2;
            split16(v.x, hx, lx); split16(v.y, hy, ly);
            split16(v.z, hz, lz); split16(v.w, hw2, lw2);
            __half2 h0 = __halves2half2(hx, hy), h1 = __halves2half2(hz, hw2);
            __half2 l0 = __halves2half2(lx, ly), l1 = __halves2half2(lz, lw2);
            int base = buf * ST_A + aRow[i] * 12 + aKq[i] * 2;
            AH[base]     = *(uint32_t*)&h0;
            AH[base + 1] = *(uint32_t*)&h1;
            AL[base]     = *(uint32_t*)&l0;
            AL[base + 1] = *(uint32_t*)&l1;
        }
    };
    auto issueB = [&](int k0, int buf) {
#pragma unroll
        for (int i = 0; i < 6; i++) {
            const __half* src = (bArr[i] ? Blo : Bhi) + (size_t)bN[i] * K + k0 + bC[i] * 8;
            uint32_t* dstA = bArr[i] ? BL : BH;
            uint32_t dst = (uint32_t)__cvta_generic_to_shared(
                dstA + buf * ST_B + bN[i] * 12 + bC[i] * 4);
            cpasync16(dst, src);
        }
        CP_COMMIT();
    };

    loadA(0);
    issueB(0, 0);
    storeA(0);
    CP_WAIT0();
    __syncthreads();
    int cur = 0;
    for (int k0 = 16; k0 < K; k0 += 16) {
        loadA(k0);
        issueB(k0, cur ^ 1);
        {
            uint32_t so = cur ? 0u : 0u;   // (compute addresses below)
            (void)so;
            uint32_t aoff = cur * (ST_A * 4);
            uint32_t boff = cur * (ST_B * 4);
            COMPUTE_TILE(aH0 + aoff, aH1 + aoff, aL0 + aoff, aL1 + aoff,
                         bHa + boff, bLa + boff, acc);
        }
        storeA(cur ^ 1);
        CP_WAIT0();
        __syncthreads();
        cur ^= 1;
    }
    {
        uint32_t aoff = cur * (ST_A * 4);
        uint32_t boff = cur * (ST_B * 4);
        COMPUTE_TILE(aH0 + aoff, aH1 + aoff, aL0 + aoff, aL1 + aoff,
                     bHa + boff, bLa + boff, acc);
    }

    // epilogue: +bias, LayerNorm, fp16 hi/lo output
    const int lrb = mw * 32 + g;
    float* smf = (float*)smu;
    float s1[4] = {0.f, 0.f, 0.f, 0.f}, s2[4] = {0.f, 0.f, 0.f, 0.f};
#pragma unroll
    for (int nt = 0; nt < 12; nt++) {
        int c = nw * 96 + nt * 8 + 2 * tg;
        float b0 = __ldg(&bias[c]), b1 = __ldg(&bias[c + 1]);
#pragma unroll
        for (int i = 0; i < 4; i++) {
            float v0 = acc[nt][2 * i]     + b0;
            float v1 = acc[nt][2 * i + 1] + b1;
            acc[nt][2 * i]     = v0;
            acc[nt][2 * i + 1] = v1;
            s1[i] += v0 + v1;
            s2[i] += v0 * v0 + v1 * v1;
        }
    }
#pragma unroll
    for (int o = 1; o < 4; o <<= 1) {
#pragma unroll
        for (int i = 0; i < 4; i++) {
            s1[i] += __shfl_xor_sync(0xffffffffu, s1[i], o);
            s2[i] += __shfl_xor_sync(0xffffffffu, s2[i], o);
        }
    }
    __syncthreads();
    if (tg == 0) {
#pragma unroll
        for (int i = 0; i < 4; i++) {
            int lr = lrb + 8 * i;
            smf[nw * 64 + lr]       = s1[i];
            smf[128 + nw * 64 + lr] = s2[i];
        }
    }
    __syncthreads();
    float mu[4], inv[4];
#pragma unroll
    for (int i = 0; i < 4; i++) {
        int lr = lrb + 8 * i;
        float S1 = smf[lr] + smf[64 + lr];
        float S2 = smf[128 + lr] + smf[192 + lr];
        mu[i]  = S1 * (1.0f / 192.0f);
        inv[i] = rsqrtf(S2 * (1.0f / 192.0f) - mu[i] * mu[i] + 1e-5f);
    }
#pragma unroll
    for (int nt = 0; nt < 12; nt++) {
        int c = nw * 96 + nt * 8 + 2 * tg;
        float gg0 = __ldg(&lng[c]), gg1 = __ldg(&lng[c + 1]);
        float bb0 = __ldg(&lnb[c]), bb1 = __ldg(&lnb[c + 1]);
#pragma unroll
        for (int i = 0; i < 4; i++) {
            int mr = bm + lrb + 8 * i;
            float o0 = (acc[nt][2 * i]     - mu[i]) * inv[i] * gg0 + bb0;
            float o1 = (acc[nt][2 * i + 1] - mu[i]) * inv[i] * gg1 + bb1;
            __half h0, l0, h1, l1;
            split16(o0, h0, l0);
            split16(o1, h1, l1);
            __half2 hh = __halves2half2(h0, h1);
            __half2 ll = __halves2half2(l0, l1);
            *(__half2*)(Ch + (size_t)mr * N + c) = hh;
            *(__half2*)(Cl + (size_t)mr * N + c) = ll;
        }
    }
}

// ================= k_mma2: pre-split fp16 A & B, cp.async, 2-stage ==========
// MODE 1/2: xPos up/down -> fp32 C   MODE 3: plain fp32 C
// MODE 4: +bias +x residual (gathered rows) -> fp32 C
template <int MODE>
__global__ void __launch_bounds__(128, 3) k_mma2(
    const __half* __restrict__ Ahi, const __half* __restrict__ Alo,
    const __half* __restrict__ Bhi, const __half* __restrict__ Blo,
    const float* __restrict__ bias, const float* __restrict__ xres,
    float* __restrict__ C, int N)
{
    const int K = DH;            // 192 -> 12 k-tiles
    extern __shared__ uint32_t smu[];
    uint32_t* AH = smu;
    uint32_t* AL = smu + 2*ST_A;
    uint32_t* BH = smu + 4*ST_A;
    uint32_t* BL = smu + 4*ST_A + 2*ST_B;

    const int tid  = threadIdx.x;
    const int w    = tid >> 5;
    const int lane = tid & 31;
    const int g    = lane >> 2;
    const int tg   = lane & 3;
    const int mw   = w >> 1;
    const int nw   = w & 1;
    const int bm   = blockIdx.y * 64;
    const int bn   = blockIdx.x * 192;

    const int aRowL = (lane & 15);
    const int aOff4 = (lane >> 4) * 4;
    uint32_t aH0 = (uint32_t)__cvta_generic_to_shared(
        AH + (mw * 32 + aRowL) * 12 + aOff4);
    uint32_t aH1 = aH0 + 16 * 48;
    uint32_t aL0 = aH0 + 2 * ST_A * 4;
    uint32_t aL1 = aL0 + 16 * 48;
    const int bRowL = (lane & 7) + ((lane & 16) >> 1);
    const int bOff4 = (lane & 8) >> 1;
    uint32_t bHa = (uint32_t)__cvta_generic_to_shared(
        BH + (nw * 96 + bRowL) * 12 + bOff4);
    uint32_t bLa = bHa + 2 * ST_B * 4;

    // cp.async slots
    int aArr[2], aR[2], aC[2];
#pragma unroll
    for (int i = 0; i < 2; i++) {
        int f = tid + i * 128;
        aArr[i] = f >> 7;
        int r = f & 127;
        aR[i] = r >> 1;
        aC[i] = r & 1;
    }
    int bArr[6], bN[6], bC[6];
#pragma unroll
    for (int i = 0; i < 6; i++) {
        int f = tid + i * 128;
        bArr[i] = f / 384;
        int r = f % 384;
        bN[i] = r >> 1;
        bC[i] = r & 1;
    }

    float acc[12][8];
#pragma unroll
    for (int nt = 0; nt < 12; nt++)
#pragma unroll
        for (int e = 0; e < 8; e++) acc[nt][e] = 0.0f;

    auto issueAB = [&](int k0, int buf) {
#pragma unroll
        for (int i = 0; i < 2; i++) {
            const __half* src = (aArr[i] ? Alo : Ahi)
                              + (size_t)(bm + aR[i]) * K + k0 + aC[i] * 8;
            uint32_t* dstA = aArr[i] ? AL : AH;
            uint32_t dst = (uint32_t)__cvta_generic_to_shared(
                dstA + buf * ST_A + aR[i] * 12 + aC[i] * 4);
            cpasync16(dst, src);
        }
#pragma unroll
        for (int i = 0; i < 6; i++) {
            const __half* src = (bArr[i] ? Blo : Bhi)
                              + (size_t)(bn + bN[i]) * K + k0 + bC[i] * 8;
            uint32_t* dstA = bArr[i] ? BL : BH;
            uint32_t dst = (uint32_t)__cvta_generic_to_shared(
                dstA + buf * ST_B + bN[i] * 12 + bC[i] * 4);
            cpasync16(dst, src);
        }
        CP_COMMIT();
    };

    issueAB(0, 0);
    CP_WAIT0();
    __syncthreads();
#pragma unroll
    for (int t = 0; t < 12; t++) {
        if (t + 1 < 12) issueAB((t + 1) * 16, (t + 1) & 1);
        uint32_t aoff = (t & 1) * (ST_A * 4);
        uint32_t boff = (t & 1) * (ST_B * 4);
        COMPUTE_TILE(aH0 + aoff, aH1 + aoff, aL0 + aoff, aL1 + aoff,
                     bHa + boff, bLa + boff, acc);
        CP_WAIT0();
        __syncthreads();
    }

    // ---------------- epilogue ----------------
    const int lrb = mw * 32 + g;

    if (MODE == 1 || MODE == 2) {
        const float* ct = (MODE == 1) ? g_cos_u : g_cos_d;
        const float* st = (MODE == 1) ? g_sin_u : g_sin_d;
#pragma unroll
        for (int nt = 0; nt < 12; nt++) {
            int c = nw * 96 + nt * 8 + 2 * tg;
            int p = (c >> 1);
#pragma unroll
            for (int i = 0; i < 4; i++) {
                int lr = lrb + 8 * i;
                int t  = lr & 31;
                float cc = ct[t * HALF + p], ss = st[t * HALF + p];
                float e = acc[nt][2 * i], od = acc[nt][2 * i + 1];
                *(float2*)(C + (size_t)(bm + lr) * N + c) =
                    make_float2(e * cc - od * ss, od * cc + e * ss);
            }
        }
    } else if (MODE == 3) {
#pragma unroll
        for (int nt = 0; nt < 12; nt++) {
            int c = nw * 96 + nt * 8 + 2 * tg;
#pragma unroll
            for (int i = 0; i < 4; i++) {
                int mr = bm + lrb + 8 * i;
                *(float2*)(C + (size_t)mr * N + c) =
                    make_float2(acc[nt][2 * i], acc[nt][2 * i + 1]);
            }
        }
    } else { // MODE 4
        int grr[4];
#pragma unroll
        for (int i = 0; i < 4; i++) grr[i] = x_row_of(bm + lrb + 8 * i);
#pragma unroll
        for (int nt = 0; nt < 12; nt++) {
            int c = bn + nw * 96 + nt * 8 + 2 * tg;
            float b0 = __ldg(&bias[c]), b1 = __ldg(&bias[c + 1]);
#pragma unroll
            for (int i = 0; i < 4; i++) {
                float2 xv = *(const float2*)(xres + (size_t)grr[i] * N + c);
                *(float2*)(C + (size_t)grr[i] * N + c) =
                    make_float2(acc[nt][2 * i] + b0 + xv.x,
                                acc[nt][2 * i + 1] + b1 + xv.y);
            }
        }
    }
}

// ---------------- per-sequence retention attention (fp16 hi/lo output) ------
__global__ void __launch_bounds__(256) k_attn(
    const float* __restrict__ Q, const float* __restrict__ Kmat,
    const float* __restrict__ V,
    __half* __restrict__ Rh, __half* __restrict__ Rl)
{
    __shared__ __align__(16) float sKV[SEQ][DH];
    const int q   = blockIdx.x;
    const int tid = threadIdx.x;
    const int n   = tid >> 3;
    const int j   = tid & 7;
    const size_t base = (size_t)q * SEQ * DH;

    for (int i = tid; i < SEQ * DH / 4; i += 256)
        ((float4*)&sKV[0][0])[i] = ((const float4*)(Kmat + base))[i];

    float qr[24];
    const float* qp = Q + base + (size_t)n * DH + j * 24;
#pragma unroll
    for (int dd = 0; dd < 6; dd++)
        *(float4*)&qr[dd * 4] = *(const float4*)(qp + dd * 4);
    __syncthreads();

    float att[SEQ];
#pragma unroll
    for (int m = 0; m < SEQ; m++) {
        float s = 0.0f;
#pragma unroll
        for (int dd = 0; dd < 6; dd++) {
            float4 kv = *(const float4*)&sKV[m][j * 24 + dd * 4];
            s += qr[dd*4+0]*kv.x + qr[dd*4+1]*kv.y + qr[dd*4+2]*kv.z + qr[dd*4+3]*kv.w;
        }
        att[m] = s;
    }
#pragma unroll
    for (int m = 0; m < SEQ; m++) {
#pragma unroll
        for (int o = 1; o < 8; o <<= 1)
            att[m] += __shfl_xor_sync(0xffffffffu, att[m], o);
        att[m] = (n >= m) ? ldexpf(att[m], m - n) : 0.0f;
    }

    __syncthreads();
    for (int i = tid; i < SEQ * DH / 4; i += 256)
        ((float4*)&sKV[0][0])[i] = ((const float4*)(V + base))[i];
    __syncthreads();

    float acc[24];
#pragma unroll
    for (int dd = 0; dd < 24; dd++) acc[dd] = 0.0f;
#pragma unroll
    for (int m = 0; m < SEQ; m++) {
        float a = att[m];
#pragma unroll
        for (int dd = 0; dd < 6; dd++) {
            float4 vv = *(const float4*)&sKV[m][j * 24 + dd * 4];
            acc[dd*4+0] += a * vv.x; acc[dd*4+1] += a * vv.y;
            acc[dd*4+2] += a * vv.z; acc[dd*4+3] += a * vv.w;
        }
    }
    size_t ro = base + (size_t)n * DH + j * 24;
#pragma unroll
    for (int dd = 0; dd < 12; dd++) {
        float v0 = acc[dd * 2], v1 = acc[dd * 2 + 1];
        __half h0, l0, h1, l1;
        split16(v0, h0, l0);
        split16(v1, h1, l1);
        __half2 hh = __halves2half2(h0, h1);
        __half2 ll = __halves2half2(l0, l1);
        *(__half2*)(Rh + ro + dd * 2) = hh;
        *(__half2*)(Rl + ro + dd * 2) = ll;
    }
}

// ---------------- launch --------------------------------------------------
extern "C" void kernel_launch(void* const* d_in, const int* in_sizes, int n_in,
                              void* d_out, int out_size)
{
    const float* x    = (const float*)d_in[0];
    const float* W1   = (const float*)d_in[1];
    const float* b1   = (const float*)d_in[2];
    const float* W2   = (const float*)d_in[3];
    const float* b2   = (const float*)d_in[4];
    const float* ln_g = (const float*)d_in[5];
    const float* ln_b = (const float*)d_in[6];
    const float* WQ   = (const float*)d_in[7];
    const float* WK   = (const float*)d_in[8];
    const float* WV   = (const float*)d_in[9];
    float* out = (float*)d_out;

    float* qb = nullptr; cudaGetSymbolAddress((void**)&qb, g_q);
    float* kb = nullptr; cudaGetSymbolAddress((void**)&kb, g_k);
    float* vb = nullptr; cudaGetSymbolAddress((void**)&vb, g_v);
    __half *xdh, *xdl, *rth, *rtl;
    cudaGetSymbolAddress((void**)&xdh, g_xdh); cudaGetSymbolAddress((void**)&xdl, g_xdl);
    cudaGetSymbolAddress((void**)&rth, g_rth); cudaGetSymbolAddress((void**)&rtl, g_rtl);
    __half *w1h, *w1l, *wqh, *wql, *wkh, *wkl, *wvh, *wvl, *w2h, *w2l;
    cudaGetSymbolAddress((void**)&w1h, g_w1h); cudaGetSymbolAddress((void**)&w1l, g_w1l);
    cudaGetSymbolAddress((void**)&wqh, g_wqh); cudaGetSymbolAddress((void**)&wql, g_wql);
    cudaGetSymbolAddress((void**)&wkh, g_wkh); cudaGetSymbolAddress((void**)&wkl, g_wkl);
    cudaGetSymbolAddress((void**)&wvh, g_wvh); cudaGetSymbolAddress((void**)&wvl, g_wvl);
    cudaGetSymbolAddress((void**)&w2h, g_w2h); cudaGetSymbolAddress((void**)&w2l, g_w2l);

    const int SMEM = SMEM_U32 * 4;   // 49152
    cudaFuncSetAttribute(k_g1,      cudaFuncAttributeMaxDynamicSharedMemorySize, SMEM);
    cudaFuncSetAttribute(k_mma2<1>, cudaFuncAttributeMaxDynamicSharedMemorySize, SMEM);
    cudaFuncSetAttribute(k_mma2<2>, cudaFuncAttributeMaxDynamicSharedMemorySize, SMEM);
    cudaFuncSetAttribute(k_mma2<3>, cudaFuncAttributeMaxDynamicSharedMemorySize, SMEM);
    cudaFuncSetAttribute(k_mma2<4>, cudaFuncAttributeMaxDynamicSharedMemorySize, SMEM);

    // prep: weight fp16 split + transpose + xPos tables
    {
        int total = DD*DH + 3*DH*DH + DH*DD + SEQ*HALF;
        k_prep<<<(total + 255) / 256, 256>>>(W1, WQ, WK, WV, W2);
    }

    // GEMM1 + bias + LN -> fp16 hi/lo h
    k_g1<<<dim3(1, MTOT / 64), 128, SMEM>>>(x, w1h, w1l, b1, ln_g, ln_b, xdh, xdl);
    // QKV from pre-split h
    k_mma2<1><<<dim3(1, MTOT / 64), 128, SMEM>>>(xdh, xdl, wqh, wql, nullptr, nullptr, qb, DH);
    k_mma2<2><<<dim3(1, MTOT / 64), 128, SMEM>>>(xdh, xdl, wkh, wkl, nullptr, nullptr, kb, DH);
    k_mma2<3><<<dim3(1, MTOT / 64), 128, SMEM>>>(xdh, xdl, wvh, wvl, nullptr, nullptr, vb, DH);
    // attention -> fp16 hi/lo ret
    k_attn<<<NSEQ, 256>>>(qb, kb, vb, rth, rtl);
    // GEMM2 from pre-split ret: +b2 +x residual -> out
    k_mma2<4><<<dim3(DD / 192, MTOT / 64), 128, SMEM>>>(rth, rtl, w2h, w2l, b2, x, out, DD);
}